// round 13
// baseline (speedup 1.0000x reference)
#include <cuda_runtime.h>
#include <cuda_fp16.h>
#include <cstdint>

#define T_TOK   4096
#define DMODEL  1024
#define DFF     4096
#define N_EXP   8
#define HCAP    9216
#define STAGES      3
#define A_STAGE     16384                // 128 rows x 64 k x fp16 (128B rows)
#define B_STAGE     16384                // 64 k-rows x 128 n x fp16 (256B rows)
#define STAGE_BYTES (A_STAGE + B_STAGE)  // 32 KB

// ---------------- device scratch (static) ----------------
__device__ int    g_cnt[N_EXP];
__device__ int    g_off[N_EXP + 1];
__device__ int    g_tok[N_EXP][T_TOK];
__device__ float  g_gate[N_EXP][T_TOK];
__device__ int    g_slot[N_EXP][T_TOK];
__device__ __half g_x16[(size_t)T_TOK * DMODEL];
__device__ __half g_h16[(size_t)HCAP * DFF];
__device__ __half g_w1h[(size_t)N_EXP * DMODEL * DFF];   // [e][d][h] native, fp16
__device__ __half g_w2h[(size_t)N_EXP * DFF * DMODEL];   // [e][h][d] native, fp16
__device__ float  g_y[2][(size_t)T_TOK * DMODEL];

// ---------------- helpers ----------------
__device__ __forceinline__ uint32_t smem_u32(const void* p) {
    uint32_t a;
    asm("{ .reg .u64 t; cvta.to.shared.u64 t, %1; cvt.u32.u64 %0, t; }" : "=r"(a) : "l"(p));
    return a;
}
__device__ __forceinline__ float geluf(float x) {
    float u = x + 0.044715f * x * x * x;
    return x / (1.0f + __expf(-1.5957691216057308f * u));
}
__device__ __forceinline__ void cpa16(uint32_t s, const void* g) {
    asm volatile("cp.async.cg.shared.global [%0], [%1], 16;\n" :: "r"(s), "l"(g));
}
__device__ __forceinline__ void ldmx4(uint32_t r[4], uint32_t addr) {
    asm volatile("ldmatrix.sync.aligned.m8n8.x4.shared.b16 {%0,%1,%2,%3}, [%4];"
                 : "=r"(r[0]), "=r"(r[1]), "=r"(r[2]), "=r"(r[3]) : "r"(addr));
}
__device__ __forceinline__ void ldmx4t(uint32_t r[4], uint32_t addr) {
    asm volatile("ldmatrix.sync.aligned.m8n8.x4.trans.shared.b16 {%0,%1,%2,%3}, [%4];"
                 : "=r"(r[0]), "=r"(r[1]), "=r"(r[2]), "=r"(r[3]) : "r"(addr));
}
__device__ __forceinline__ void mma_f16(float c[4], const uint32_t a[4],
                                        uint32_t b0, uint32_t b1) {
    asm volatile(
        "mma.sync.aligned.m16n8k16.row.col.f32.f16.f16.f32 "
        "{%0,%1,%2,%3}, {%4,%5,%6,%7}, {%8,%9}, {%0,%1,%2,%3};\n"
        : "+f"(c[0]), "+f"(c[1]), "+f"(c[2]), "+f"(c[3])
        : "r"(a[0]), "r"(a[1]), "r"(a[2]), "r"(a[3]), "r"(b0), "r"(b1));
}

// ---------------- small kernels ----------------

// streaming fp32 -> fp16 (same layout), 8 elems / thread, 16B stores.
// which==0 additionally resets the router counters (block 0).
__global__ void convert_w_kernel(const float* __restrict__ in, int which) {
    if (which == 0 && blockIdx.x == 0 && threadIdx.x < N_EXP)
        g_cnt[threadIdx.x] = 0;
    __half* out = which ? g_w2h : g_w1h;
    size_t i = ((size_t)blockIdx.x * 256 + threadIdx.x) * 8;
    float4 v0 = *reinterpret_cast<const float4*>(in + i);
    float4 v1 = *reinterpret_cast<const float4*>(in + i + 4);
    half2 h[4];
    h[0] = __floats2half2_rn(v0.x, v0.y); h[1] = __floats2half2_rn(v0.z, v0.w);
    h[2] = __floats2half2_rn(v1.x, v1.y); h[3] = __floats2half2_rn(v1.z, v1.w);
    *reinterpret_cast<uint4*>(out + i) = *reinterpret_cast<uint4*>(h);
}

// router + fused x -> fp16 conversion
__global__ void router_kernel(const float* __restrict__ x, const float* __restrict__ Wg) {
    const int t = blockIdx.x, tid = threadIdx.x;
    float acc[8];
#pragma unroll
    for (int e = 0; e < 8; e++) acc[e] = 0.0f;
    const float* xr = x + (size_t)t * DMODEL;
    __half* x16r = g_x16 + (size_t)t * DMODEL;
    for (int d = tid; d < DMODEL; d += 128) {
        float xv = xr[d];
        x16r[d] = __float2half_rn(xv);
        const float4* w4 = reinterpret_cast<const float4*>(Wg + (size_t)d * 8);
        float4 w0 = w4[0], w1 = w4[1];
        acc[0] += xv * w0.x; acc[1] += xv * w0.y; acc[2] += xv * w0.z; acc[3] += xv * w0.w;
        acc[4] += xv * w1.x; acc[5] += xv * w1.y; acc[6] += xv * w1.z; acc[7] += xv * w1.w;
    }
#pragma unroll
    for (int e = 0; e < 8; e++)
#pragma unroll
        for (int o = 16; o > 0; o >>= 1) acc[e] += __shfl_down_sync(0xffffffffu, acc[e], o);
    __shared__ float sred[4][8];
    int wid = tid >> 5, lane = tid & 31;
    if (lane == 0)
#pragma unroll
        for (int e = 0; e < 8; e++) sred[wid][e] = acc[e];
    __syncthreads();
    if (tid == 0) {
        float l[8];
#pragma unroll
        for (int e = 0; e < 8; e++) l[e] = sred[0][e] + sred[1][e] + sred[2][e] + sred[3][e];
        int i1 = 0;
#pragma unroll
        for (int e = 1; e < 8; e++) if (l[e] > l[i1]) i1 = e;
        int i2 = (i1 == 0) ? 1 : 0;
#pragma unroll
        for (int e = 0; e < 8; e++) if (e != i1 && l[e] > l[i2]) i2 = e;
        float m = l[i1], p[8], s = 0.0f;
#pragma unroll
        for (int e = 0; e < 8; e++) { p[e] = __expf(l[e] - m); s += p[e]; }
        float inv = 1.0f / s;
        int pos1 = atomicAdd(&g_cnt[i1], 1);
        g_tok[i1][pos1] = t; g_gate[i1][pos1] = p[i1] * inv; g_slot[i1][pos1] = 0;
        int pos2 = atomicAdd(&g_cnt[i2], 1);
        g_tok[i2][pos2] = t; g_gate[i2][pos2] = p[i2] * inv; g_slot[i2][pos2] = 1;
    }
}

__global__ void scan_kernel() {
    if (threadIdx.x == 0) {
        int o = 0;
#pragma unroll
        for (int e = 0; e < N_EXP; e++) { g_off[e] = o; o += (g_cnt[e] + 127) & ~127; }
        g_off[N_EXP] = o;
    }
}

__global__ void combine_kernel(float* __restrict__ out) {
    size_t i = ((size_t)blockIdx.x * 256 + threadIdx.x) * 4;
    float4 a = *reinterpret_cast<const float4*>(&g_y[0][i]);
    float4 b = *reinterpret_cast<const float4*>(&g_y[1][i]);
    *reinterpret_cast<float4*>(out + i) =
        make_float4(a.x + b.x, a.y + b.y, a.z + b.z, a.w + b.w);
}

// ---------------- fp16 grouped GEMM: 128(M) x 128(N) x 64(K), 3-stage, 2 CTA/SM ------
// ONE __syncthreads per k-tile (16 for GEMM1, 64 for GEMM2). The write target of
// issue(kt+2) is stage (kt-1)%3, whose readers finished before this iteration's
// leading sync, so no trailing sync is needed.
template <bool FIRST>
__global__ void __launch_bounds__(256, 2)
moe_gemm_fp16(const float* __restrict__ bias) {
    constexpr int KTOT = FIRST ? DMODEL : DFF;
    constexpr int NDIM = FIRST ? DFF : DMODEL;
    constexpr int KT   = KTOT / 64;

    const int e = blockIdx.z;
    const int cnt = g_cnt[e];
    const int mtile = blockIdx.y;
    if (mtile * 128 >= cnt) return;
    const int ntile = blockIdx.x;
    const int roff = g_off[e];

    extern __shared__ __align__(1024) char smraw[];
    const uint32_t smem_u = smem_u32(smraw);

    const int tid = threadIdx.x;
    const int lane = tid & 31, wid = tid >> 5;
    const int warp_m = (wid & 1) * 64;       // {0,64}
    const int warp_n = (wid >> 1) * 32;      // {0,32,64,96}

    // ---- cp.async staging ----
    // A: 128 rows x 128B (8 chunks/row); thread -> (row, 4 chunks)
    const int arow = tid >> 1;
    const int ac0 = (tid & 1) * 4;
    const __half* aptr;
    if (FIRST) {
        int li = mtile * 128 + arow;
        int tok = (li < cnt) ? g_tok[e][li] : g_tok[e][0];
        aptr = g_x16 + (size_t)tok * DMODEL + ac0 * 8;
    } else {
        aptr = g_h16 + (size_t)(roff + mtile * 128 + arow) * DFF + ac0 * 8;
    }
    uint32_t adst[4];
#pragma unroll
    for (int j = 0; j < 4; j++) {
        int c = ac0 + j;
        adst[j] = (uint32_t)(arow * 128 + ((c ^ (arow & 7)) << 4));
    }
    // B: 64 k-rows x 256B (16 chunks/row); thread -> (row, 4 chunks)
    const int brow = tid >> 2;
    const int bc0 = (tid & 3) * 4;
    const __half* bptr = (FIRST ? g_w1h : g_w2h)
        + (size_t)e * KTOT * NDIM + (size_t)brow * NDIM + ntile * 128 + bc0 * 8;
    uint32_t bdst[4];
#pragma unroll
    for (int j = 0; j < 4; j++) {
        int c = bc0 + j;
        bdst[j] = (uint32_t)(A_STAGE + brow * 256 + ((c ^ (brow & 7)) << 4));
    }

    auto issue = [&](int kt) {
        uint32_t base = smem_u + (kt % 3) * STAGE_BYTES;
        const __half* as = aptr + kt * 64;
        const __half* bs = bptr + (size_t)kt * 64 * NDIM;
#pragma unroll
        for (int j = 0; j < 4; j++) cpa16(base + adst[j], as + j * 8);
#pragma unroll
        for (int j = 0; j < 4; j++) cpa16(base + bdst[j], bs + j * 8);
        asm volatile("cp.async.commit_group;\n");
    };

    // ---- ldmatrix address precompute ----
    const int ahi = lane >> 4;              // 0/1 -> k chunk select
    uint32_t aoff[4], aswz[4];
#pragma unroll
    for (int mf = 0; mf < 4; mf++) {
        int row = warp_m + mf * 16 + (lane & 15);
        aoff[mf] = (uint32_t)(row * 128);
        aswz[mf] = (uint32_t)(row & 7);
    }
    const uint32_t brow_l = (uint32_t)((lane & 15) * 256);
    uint32_t bcol[2];
#pragma unroll
    for (int nb = 0; nb < 2; nb++) {
        int chunk = (warp_n >> 3) + nb * 2 + (lane >> 4);
        bcol[nb] = (uint32_t)(A_STAGE + ((chunk ^ (lane & 7)) << 4));
    }

    float acc[4][4][4];
#pragma unroll
    for (int a = 0; a < 4; a++)
#pragma unroll
        for (int b = 0; b < 4; b++)
#pragma unroll
            for (int c = 0; c < 4; c++) acc[a][b][c] = 0.0f;

    issue(0); issue(1);

    for (int kt = 0; kt < KT; kt++) {
        if (kt < KT - 1) asm volatile("cp.async.wait_group 1;\n");
        else             asm volatile("cp.async.wait_group 0;\n");
        __syncthreads();
        if (kt + 2 < KT) issue(kt + 2);
        const uint32_t base = smem_u + (kt % 3) * STAGE_BYTES;

#pragma unroll
        for (int ks = 0; ks < 4; ks++) {
            uint32_t a[4][4];
#pragma unroll
            for (int mf = 0; mf < 4; mf++)
                ldmx4(a[mf], base + aoff[mf] + ((uint32_t)((2 * ks + ahi) ^ aswz[mf]) << 4));
            uint32_t b[2][4];
#pragma unroll
            for (int nb = 0; nb < 2; nb++)
                ldmx4t(b[nb], base + brow_l + ks * 4096 + bcol[nb]);
#pragma unroll
            for (int mf = 0; mf < 4; mf++)
#pragma unroll
                for (int nb = 0; nb < 2; nb++) {
                    mma_f16(acc[mf][2 * nb + 0], a[mf], b[nb][0], b[nb][1]);
                    mma_f16(acc[mf][2 * nb + 1], a[mf], b[nb][2], b[nb][3]);
                }
        }
    }

    // ---- epilogue ----
    const float* bp = bias + (size_t)e * NDIM + (size_t)ntile * 128;
    const int mlo = lane >> 2;
    const int ncol = (lane & 3) * 2;

    if (FIRST) {
#pragma unroll
        for (int mf = 0; mf < 4; mf++) {
#pragma unroll
            for (int half = 0; half < 2; half++) {
                int row = roff + mtile * 128 + warp_m + mf * 16 + mlo + half * 8;
                __half* hr = g_h16 + (size_t)row * DFF + (size_t)ntile * 128;
#pragma unroll
                for (int nf = 0; nf < 4; nf++) {
                    int c = warp_n + nf * 8 + ncol;
                    float v0 = geluf(acc[mf][nf][half * 2 + 0] + bp[c]);
                    float v1 = geluf(acc[mf][nf][half * 2 + 1] + bp[c + 1]);
                    *reinterpret_cast<half2*>(hr + c) = __floats2half2_rn(v0, v1);
                }
            }
        }
    } else {
#pragma unroll
        for (int mf = 0; mf < 4; mf++) {
#pragma unroll
            for (int half = 0; half < 2; half++) {
                int li = mtile * 128 + warp_m + mf * 16 + mlo + half * 8;
                if (li < cnt) {
                    int   t  = g_tok[e][li];
                    float w  = g_gate[e][li];
                    int   sl = g_slot[e][li];
                    float* orow = &g_y[sl][(size_t)t * DMODEL + (size_t)ntile * 128];
#pragma unroll
                    for (int nf = 0; nf < 4; nf++) {
                        int c = warp_n + nf * 8 + ncol;
                        float2 v;
                        v.x = (acc[mf][nf][half * 2 + 0] + bp[c])     * w;
                        v.y = (acc[mf][nf][half * 2 + 1] + bp[c + 1]) * w;
                        *reinterpret_cast<float2*>(orow + c) = v;
                    }
                }
            }
        }
    }
}

// ---------------- launch ----------------
extern "C" void kernel_launch(void* const* d_in, const int* in_sizes, int n_in,
                              void* d_out, int out_size) {
    const float* x  = (const float*)d_in[0];
    const float* Wg = (const float*)d_in[1];
    const float* W1 = (const float*)d_in[2];
    const float* b1 = (const float*)d_in[3];
    const float* W2 = (const float*)d_in[4];
    const float* b2 = (const float*)d_in[5];
    float* out = (float*)d_out;

    const int smem_bytes = STAGES * STAGE_BYTES;   // 96 KB
    cudaFuncSetAttribute(moe_gemm_fp16<true>,  cudaFuncAttributeMaxDynamicSharedMemorySize, smem_bytes);
    cudaFuncSetAttribute(moe_gemm_fp16<false>, cudaFuncAttributeMaxDynamicSharedMemorySize, smem_bytes);

    const int wblocks = (N_EXP * DMODEL * DFF) / (256 * 8);
    // Launch order keeps moe_gemm_fp16<true> at position 4 (the ncu window).
    convert_w_kernel<<<wblocks, 256>>>(W1, 0);   // 1 (also resets g_cnt)
    router_kernel<<<T_TOK, 128>>>(x, Wg);        // 2
    scan_kernel<<<1, 1>>>();                     // 3
    moe_gemm_fp16<true ><<<dim3(DFF / 128,    32, N_EXP), 256, smem_bytes>>>(b1);  // 4
    convert_w_kernel<<<wblocks, 256>>>(W2, 1);   // 5
    moe_gemm_fp16<false><<<dim3(DMODEL / 128, 32, N_EXP), 256, smem_bytes>>>(b2);  // 6
    combine_kernel<<<(T_TOK * DMODEL) / 1024, 256>>>(out);                         // 7
}

// round 14
// speedup vs baseline: 1.1127x; 1.1127x over previous
#include <cuda_runtime.h>
#include <cuda_fp16.h>
#include <cstdint>

#define T_TOK   4096
#define DMODEL  1024
#define DFF     4096
#define N_EXP   8
#define HCAP    9216
#define STAGES      4
#define A_STAGE     8192                 // 128 rows x 32 k x fp16
#define B_STAGE     8192                 // 32 k-rows x 128 n x fp16
#define STAGE_BYTES (A_STAGE + B_STAGE)  // 16 KB

// ---------------- device scratch (static) ----------------
__device__ int    g_cnt[N_EXP];
__device__ int    g_off[N_EXP + 1];
__device__ int    g_tok[N_EXP][T_TOK];
__device__ float  g_gate[N_EXP][T_TOK];
__device__ int    g_slot[N_EXP][T_TOK];
__device__ __half g_x16[(size_t)T_TOK * DMODEL];
__device__ __half g_h16[(size_t)HCAP * DFF];
__device__ __half g_w1h[(size_t)N_EXP * DMODEL * DFF];   // [e][d][h] native, fp16
__device__ __half g_w2h[(size_t)N_EXP * DFF * DMODEL];   // [e][h][d] native, fp16
__device__ float  g_y[2][(size_t)T_TOK * DMODEL];

// ---------------- helpers ----------------
__device__ __forceinline__ uint32_t smem_u32(const void* p) {
    uint32_t a;
    asm("{ .reg .u64 t; cvta.to.shared.u64 t, %1; cvt.u32.u64 %0, t; }" : "=r"(a) : "l"(p));
    return a;
}
__device__ __forceinline__ float geluf(float x) {
    float u = x + 0.044715f * x * x * x;
    return x / (1.0f + __expf(-1.5957691216057308f * u));
}
// packed-half2 GELU: x in f32 pair, poly in f32 (FMA pipe), sigmoid in half2
// (1 MUFU h2exp + 1 MUFU h2rcp per 2 outputs). Returns the half2 to store.
__device__ __forceinline__ half2 gelu_h2(float x0, float x1) {
    float u0 = 1.5957691216057308f * (x0 + 0.044715f * x0 * x0 * x0);
    float u1 = 1.5957691216057308f * (x1 + 0.044715f * x1 * x1 * x1);
    half2 hx = __floats2half2_rn(x0, x1);
    half2 hu = __floats2half2_rn(u0, u1);
    half2 e  = h2exp(__hneg2(hu));
    half2 s  = h2rcp(__hadd2(__floats2half2_rn(1.0f, 1.0f), e));
    return __hmul2(hx, s);
}
__device__ __forceinline__ void cpa16(uint32_t s, const void* g) {
    asm volatile("cp.async.cg.shared.global [%0], [%1], 16;\n" :: "r"(s), "l"(g));
}
__device__ __forceinline__ void ldmx4(uint32_t r[4], uint32_t addr) {
    asm volatile("ldmatrix.sync.aligned.m8n8.x4.shared.b16 {%0,%1,%2,%3}, [%4];"
                 : "=r"(r[0]), "=r"(r[1]), "=r"(r[2]), "=r"(r[3]) : "r"(addr));
}
__device__ __forceinline__ void ldmx4t(uint32_t r[4], uint32_t addr) {
    asm volatile("ldmatrix.sync.aligned.m8n8.x4.trans.shared.b16 {%0,%1,%2,%3}, [%4];"
                 : "=r"(r[0]), "=r"(r[1]), "=r"(r[2]), "=r"(r[3]) : "r"(addr));
}
__device__ __forceinline__ void mma_f16(float c[4], const uint32_t a[4],
                                        uint32_t b0, uint32_t b1) {
    asm volatile(
        "mma.sync.aligned.m16n8k16.row.col.f32.f16.f16.f32 "
        "{%0,%1,%2,%3}, {%4,%5,%6,%7}, {%8,%9}, {%0,%1,%2,%3};\n"
        : "+f"(c[0]), "+f"(c[1]), "+f"(c[2]), "+f"(c[3])
        : "r"(a[0]), "r"(a[1]), "r"(a[2]), "r"(a[3]), "r"(b0), "r"(b1));
}

// ---------------- small kernels ----------------

// streaming fp32 -> fp16 (same layout), 8 elems / thread, 16B stores.
// which==0 additionally resets the router counters (block 0).
__global__ void convert_w_kernel(const float* __restrict__ in, int which) {
    if (which == 0 && blockIdx.x == 0 && threadIdx.x < N_EXP)
        g_cnt[threadIdx.x] = 0;
    __half* out = which ? g_w2h : g_w1h;
    size_t i = ((size_t)blockIdx.x * 256 + threadIdx.x) * 8;
    float4 v0 = *reinterpret_cast<const float4*>(in + i);
    float4 v1 = *reinterpret_cast<const float4*>(in + i + 4);
    half2 h[4];
    h[0] = __floats2half2_rn(v0.x, v0.y); h[1] = __floats2half2_rn(v0.z, v0.w);
    h[2] = __floats2half2_rn(v1.x, v1.y); h[3] = __floats2half2_rn(v1.z, v1.w);
    *reinterpret_cast<uint4*>(out + i) = *reinterpret_cast<uint4*>(h);
}

// router + fused x -> fp16 conversion
__global__ void router_kernel(const float* __restrict__ x, const float* __restrict__ Wg) {
    const int t = blockIdx.x, tid = threadIdx.x;
    float acc[8];
#pragma unroll
    for (int e = 0; e < 8; e++) acc[e] = 0.0f;
    const float* xr = x + (size_t)t * DMODEL;
    __half* x16r = g_x16 + (size_t)t * DMODEL;
    for (int d = tid; d < DMODEL; d += 128) {
        float xv = xr[d];
        x16r[d] = __float2half_rn(xv);
        const float4* w4 = reinterpret_cast<const float4*>(Wg + (size_t)d * 8);
        float4 w0 = w4[0], w1 = w4[1];
        acc[0] += xv * w0.x; acc[1] += xv * w0.y; acc[2] += xv * w0.z; acc[3] += xv * w0.w;
        acc[4] += xv * w1.x; acc[5] += xv * w1.y; acc[6] += xv * w1.z; acc[7] += xv * w1.w;
    }
#pragma unroll
    for (int e = 0; e < 8; e++)
#pragma unroll
        for (int o = 16; o > 0; o >>= 1) acc[e] += __shfl_down_sync(0xffffffffu, acc[e], o);
    __shared__ float sred[4][8];
    int wid = tid >> 5, lane = tid & 31;
    if (lane == 0)
#pragma unroll
        for (int e = 0; e < 8; e++) sred[wid][e] = acc[e];
    __syncthreads();
    if (tid == 0) {
        float l[8];
#pragma unroll
        for (int e = 0; e < 8; e++) l[e] = sred[0][e] + sred[1][e] + sred[2][e] + sred[3][e];
        int i1 = 0;
#pragma unroll
        for (int e = 1; e < 8; e++) if (l[e] > l[i1]) i1 = e;
        int i2 = (i1 == 0) ? 1 : 0;
#pragma unroll
        for (int e = 0; e < 8; e++) if (e != i1 && l[e] > l[i2]) i2 = e;
        float m = l[i1], p[8], s = 0.0f;
#pragma unroll
        for (int e = 0; e < 8; e++) { p[e] = __expf(l[e] - m); s += p[e]; }
        float inv = 1.0f / s;
        int pos1 = atomicAdd(&g_cnt[i1], 1);
        g_tok[i1][pos1] = t; g_gate[i1][pos1] = p[i1] * inv; g_slot[i1][pos1] = 0;
        int pos2 = atomicAdd(&g_cnt[i2], 1);
        g_tok[i2][pos2] = t; g_gate[i2][pos2] = p[i2] * inv; g_slot[i2][pos2] = 1;
    }
}

__global__ void scan_kernel() {
    if (threadIdx.x == 0) {
        int o = 0;
#pragma unroll
        for (int e = 0; e < N_EXP; e++) { g_off[e] = o; o += (g_cnt[e] + 127) & ~127; }
        g_off[N_EXP] = o;
    }
}

__global__ void combine_kernel(float* __restrict__ out) {
    size_t i = ((size_t)blockIdx.x * 256 + threadIdx.x) * 4;
    float4 a = *reinterpret_cast<const float4*>(&g_y[0][i]);
    float4 b = *reinterpret_cast<const float4*>(&g_y[1][i]);
    *reinterpret_cast<float4*>(out + i) =
        make_float4(a.x + b.x, a.y + b.y, a.z + b.z, a.w + b.w);
}

// ---------------- fp16 grouped GEMM: 128(M) x 128(N) x 32(K), 4-stage, 2 CTA/SM ------
// A: K-major fp16 rows, ldmatrix normal. B: native [k][n] fp16, ldmatrix.trans.
template <bool FIRST>
__global__ void __launch_bounds__(256, 2)
moe_gemm_fp16(const float* __restrict__ bias) {
    constexpr int KTOT = FIRST ? DMODEL : DFF;
    constexpr int NDIM = FIRST ? DFF : DMODEL;
    constexpr int KT   = KTOT / 32;

    const int e = blockIdx.z;
    const int cnt = g_cnt[e];
    const int mtile = blockIdx.y;
    if (mtile * 128 >= cnt) return;
    const int ntile = blockIdx.x;
    const int roff = g_off[e];

    extern __shared__ __align__(1024) char smraw[];
    const uint32_t smem_u = smem_u32(smraw);

    const int tid = threadIdx.x;
    const int lane = tid & 31, wid = tid >> 5;
    const int warp_m = (wid & 1) * 64;       // {0,64}
    const int warp_n = (wid >> 1) * 32;      // {0,32,64,96}

    // ---- cp.async staging ----
    // A: 128 rows x 64B (4 chunks/row); thread -> (row, 2 chunks)
    const int arow = tid >> 1;
    const int ac0 = (tid & 1) * 2;
    const __half* aptr;
    if (FIRST) {
        int li = mtile * 128 + arow;
        int tok = (li < cnt) ? g_tok[e][li] : g_tok[e][0];
        aptr = g_x16 + (size_t)tok * DMODEL + ac0 * 8;
    } else {
        aptr = g_h16 + (size_t)(roff + mtile * 128 + arow) * DFF + ac0 * 8;
    }
    uint32_t adst[2];
#pragma unroll
    for (int j = 0; j < 2; j++) {
        int c = ac0 + j;
        adst[j] = (uint32_t)(arow * 64 + ((c ^ ((arow >> 1) & 3)) << 4));
    }
    // B: 32 k-rows x 256B (16 chunks/row); thread -> (row, 2 chunks)
    const int brow = tid >> 3;
    const int bc0 = (tid & 7) * 2;
    const __half* bptr = (FIRST ? g_w1h : g_w2h)
        + (size_t)e * KTOT * NDIM + (size_t)brow * NDIM + ntile * 128 + bc0 * 8;
    uint32_t bdst[2];
#pragma unroll
    for (int j = 0; j < 2; j++) {
        int c = bc0 + j;
        bdst[j] = (uint32_t)(A_STAGE + brow * 256 + ((c ^ (brow & 7)) << 4));
    }

    auto issue = [&](int kt) {
        uint32_t base = smem_u + (kt & 3) * STAGE_BYTES;
        const __half* as = aptr + kt * 32;
        const __half* bs = bptr + (size_t)kt * 32 * NDIM;
        cpa16(base + adst[0], as);
        cpa16(base + adst[1], as + 8);
        cpa16(base + bdst[0], bs);
        cpa16(base + bdst[1], bs + 8);
        asm volatile("cp.async.commit_group;\n");
    };

    // ---- ldmatrix address precompute ----
    const int ahi = lane >> 4;              // 0/1 -> k chunk select
    uint32_t aoff[4], aswz[4];
#pragma unroll
    for (int mf = 0; mf < 4; mf++) {
        int row = warp_m + mf * 16 + (lane & 15);
        aoff[mf] = (uint32_t)(row * 64);
        aswz[mf] = (uint32_t)((row >> 1) & 3);
    }
    const uint32_t brow_l = (uint32_t)((lane & 15) * 256);
    uint32_t bcol[2];
#pragma unroll
    for (int nb = 0; nb < 2; nb++) {
        int chunk = (warp_n >> 3) + nb * 2 + (lane >> 4);
        bcol[nb] = (uint32_t)(A_STAGE + ((chunk ^ (lane & 7)) << 4));
    }

    float acc[4][4][4];
#pragma unroll
    for (int a = 0; a < 4; a++)
#pragma unroll
        for (int b = 0; b < 4; b++)
#pragma unroll
            for (int c = 0; c < 4; c++) acc[a][b][c] = 0.0f;

    issue(0); issue(1); issue(2);

    for (int kt = 0; kt < KT; kt++) {
        if (kt < KT - 2)       asm volatile("cp.async.wait_group 2;\n");
        else if (kt == KT - 2) asm volatile("cp.async.wait_group 1;\n");
        else                   asm volatile("cp.async.wait_group 0;\n");
        __syncthreads();
        if (kt + 3 < KT) issue(kt + 3);
        const uint32_t base = smem_u + (kt & 3) * STAGE_BYTES;

#pragma unroll
        for (int ks = 0; ks < 2; ks++) {
            uint32_t a[4][4];
#pragma unroll
            for (int mf = 0; mf < 4; mf++)
                ldmx4(a[mf], base + aoff[mf] + ((uint32_t)((2 * ks + ahi) ^ aswz[mf]) << 4));
            uint32_t b[2][4];
#pragma unroll
            for (int nb = 0; nb < 2; nb++)
                ldmx4t(b[nb], base + brow_l + ks * 4096 + bcol[nb]);
#pragma unroll
            for (int mf = 0; mf < 4; mf++)
#pragma unroll
                for (int nb = 0; nb < 2; nb++) {
                    mma_f16(acc[mf][2 * nb + 0], a[mf], b[nb][0], b[nb][1]);
                    mma_f16(acc[mf][2 * nb + 1], a[mf], b[nb][2], b[nb][3]);
                }
        }
    }

    // ---- epilogue ----
    const float* bp = bias + (size_t)e * NDIM + (size_t)ntile * 128;
    const int mlo = lane >> 2;
    const int ncol = (lane & 3) * 2;

    if (FIRST) {
#pragma unroll
        for (int mf = 0; mf < 4; mf++) {
#pragma unroll
            for (int half = 0; half < 2; half++) {
                int row = roff + mtile * 128 + warp_m + mf * 16 + mlo + half * 8;
                __half* hr = g_h16 + (size_t)row * DFF + (size_t)ntile * 128;
#pragma unroll
                for (int nf = 0; nf < 4; nf++) {
                    int c = warp_n + nf * 8 + ncol;
                    *reinterpret_cast<half2*>(hr + c) =
                        gelu_h2(acc[mf][nf][half * 2 + 0] + bp[c],
                                acc[mf][nf][half * 2 + 1] + bp[c + 1]);
                }
            }
        }
    } else {
#pragma unroll
        for (int mf = 0; mf < 4; mf++) {
#pragma unroll
            for (int half = 0; half < 2; half++) {
                int li = mtile * 128 + warp_m + mf * 16 + mlo + half * 8;
                if (li < cnt) {
                    int   t  = g_tok[e][li];
                    float w  = g_gate[e][li];
                    int   sl = g_slot[e][li];
                    float* orow = &g_y[sl][(size_t)t * DMODEL + (size_t)ntile * 128];
#pragma unroll
                    for (int nf = 0; nf < 4; nf++) {
                        int c = warp_n + nf * 8 + ncol;
                        float2 v;
                        v.x = (acc[mf][nf][half * 2 + 0] + bp[c])     * w;
                        v.y = (acc[mf][nf][half * 2 + 1] + bp[c + 1]) * w;
                        *reinterpret_cast<float2*>(orow + c) = v;
                    }
                }
            }
        }
    }
}

// ---------------- launch ----------------
extern "C" void kernel_launch(void* const* d_in, const int* in_sizes, int n_in,
                              void* d_out, int out_size) {
    const float* x  = (const float*)d_in[0];
    const float* Wg = (const float*)d_in[1];
    const float* W1 = (const float*)d_in[2];
    const float* b1 = (const float*)d_in[3];
    const float* W2 = (const float*)d_in[4];
    const float* b2 = (const float*)d_in[5];
    float* out = (float*)d_out;

    const int smem_bytes = STAGES * STAGE_BYTES;   // 64 KB
    cudaFuncSetAttribute(moe_gemm_fp16<true>,  cudaFuncAttributeMaxDynamicSharedMemorySize, smem_bytes);
    cudaFuncSetAttribute(moe_gemm_fp16<false>, cudaFuncAttributeMaxDynamicSharedMemorySize, smem_bytes);

    const int wblocks = (N_EXP * DMODEL * DFF) / (256 * 8);
    // Launch order keeps moe_gemm_fp16<true> at position 4 (the ncu window).
    convert_w_kernel<<<wblocks, 256>>>(W1, 0);   // 1 (also resets g_cnt)
    router_kernel<<<T_TOK, 128>>>(x, Wg);        // 2
    scan_kernel<<<1, 1>>>();                     // 3
    moe_gemm_fp16<true ><<<dim3(DFF / 128,    32, N_EXP), 256, smem_bytes>>>(b1);  // 4
    convert_w_kernel<<<wblocks, 256>>>(W2, 1);   // 5
    moe_gemm_fp16<false><<<dim3(DMODEL / 128, 32, N_EXP), 256, smem_bytes>>>(b2);  // 6
    combine_kernel<<<(T_TOK * DMODEL) / 1024, 256>>>(out);                         // 7
}

// round 15
// speedup vs baseline: 1.1523x; 1.0355x over previous
#include <cuda_runtime.h>
#include <cuda_fp16.h>
#include <cstdint>

#define T_TOK   4096
#define DMODEL  1024
#define DFF     4096
#define N_EXP   8
#define HCAP    9216
#define STAGES      4
#define A_STAGE     8192                 // 128 rows x 32 k x fp16
#define B_STAGE     8192                 // 32 k-rows x 128 n x fp16
#define STAGE_BYTES (A_STAGE + B_STAGE)  // 16 KB
#define W_ELEMS ((size_t)N_EXP * DMODEL * DFF)   // 32M elements per weight tensor
#define CW1_BLOCKS 2048                  // convert-W1 blocks fused into router launch
#define CW2_BLOCKS 1024                  // convert-W2 blocks fused into GEMM1 launch (32x32 slice)

// ---------------- device scratch (static) ----------------
__device__ int    g_cnt[N_EXP];
__device__ int    g_off[N_EXP + 1];
__device__ int    g_tok[N_EXP][T_TOK];
__device__ float  g_gate[N_EXP][T_TOK];
__device__ int    g_slot[N_EXP][T_TOK];
__device__ __half g_x16[(size_t)T_TOK * DMODEL];
__device__ __half g_h16[(size_t)HCAP * DFF];
__device__ __half g_w1h[W_ELEMS];   // [e][d][h] native, fp16
__device__ __half g_w2h[W_ELEMS];   // [e][h][d] native, fp16
__device__ float  g_y[2][(size_t)T_TOK * DMODEL];

// ---------------- helpers ----------------
__device__ __forceinline__ uint32_t smem_u32(const void* p) {
    uint32_t a;
    asm("{ .reg .u64 t; cvta.to.shared.u64 t, %1; cvt.u32.u64 %0, t; }" : "=r"(a) : "l"(p));
    return a;
}
// packed-half2 GELU: poly in f32 (FMA pipe), sigmoid in half2 (2 MUFU / 2 outputs)
__device__ __forceinline__ half2 gelu_h2(float x0, float x1) {
    float u0 = 1.5957691216057308f * (x0 + 0.044715f * x0 * x0 * x0);
    float u1 = 1.5957691216057308f * (x1 + 0.044715f * x1 * x1 * x1);
    half2 hx = __floats2half2_rn(x0, x1);
    half2 hu = __floats2half2_rn(u0, u1);
    half2 e  = h2exp(__hneg2(hu));
    half2 s  = h2rcp(__hadd2(__floats2half2_rn(1.0f, 1.0f), e));
    return __hmul2(hx, s);
}
__device__ __forceinline__ void cpa16(uint32_t s, const void* g) {
    asm volatile("cp.async.cg.shared.global [%0], [%1], 16;\n" :: "r"(s), "l"(g));
}
__device__ __forceinline__ void ldmx4(uint32_t r[4], uint32_t addr) {
    asm volatile("ldmatrix.sync.aligned.m8n8.x4.shared.b16 {%0,%1,%2,%3}, [%4];"
                 : "=r"(r[0]), "=r"(r[1]), "=r"(r[2]), "=r"(r[3]) : "r"(addr));
}
__device__ __forceinline__ void ldmx4t(uint32_t r[4], uint32_t addr) {
    asm volatile("ldmatrix.sync.aligned.m8n8.x4.trans.shared.b16 {%0,%1,%2,%3}, [%4];"
                 : "=r"(r[0]), "=r"(r[1]), "=r"(r[2]), "=r"(r[3]) : "r"(addr));
}
__device__ __forceinline__ void mma_f16(float c[4], const uint32_t a[4],
                                        uint32_t b0, uint32_t b1) {
    asm volatile(
        "mma.sync.aligned.m16n8k16.row.col.f32.f16.f16.f32 "
        "{%0,%1,%2,%3}, {%4,%5,%6,%7}, {%8,%9}, {%0,%1,%2,%3};\n"
        : "+f"(c[0]), "+f"(c[1]), "+f"(c[2]), "+f"(c[3])
        : "r"(a[0]), "r"(a[1]), "r"(a[2]), "r"(a[3]), "r"(b0), "r"(b1));
}
// grid-stride fp32 -> fp16 convert, 8 elems per thread per step
__device__ __forceinline__ void convert_span(const float* __restrict__ in, __half* __restrict__ out,
                                             size_t start, size_t stride, size_t total) {
    for (size_t i = start * 8; i < total; i += stride * 8) {
        float4 v0 = *reinterpret_cast<const float4*>(in + i);
        float4 v1 = *reinterpret_cast<const float4*>(in + i + 4);
        half2 h[4];
        h[0] = __floats2half2_rn(v0.x, v0.y); h[1] = __floats2half2_rn(v0.z, v0.w);
        h[2] = __floats2half2_rn(v1.x, v1.y); h[3] = __floats2half2_rn(v1.z, v1.w);
        *reinterpret_cast<uint4*>(out + i) = *reinterpret_cast<uint4*>(h);
    }
}

// ---------------- small kernels ----------------
__global__ void reset_kernel() { if (threadIdx.x < N_EXP) g_cnt[threadIdx.x] = 0; }

// router (+ x->fp16) fused with W1 convert (blocks >= T_TOK)
__global__ void router_kernel(const float* __restrict__ x, const float* __restrict__ Wg,
                              const float* __restrict__ W1) {
    if (blockIdx.x >= T_TOK) {
        size_t b = blockIdx.x - T_TOK;
        convert_span(W1, g_w1h, b * 128 + threadIdx.x,
                     (size_t)CW1_BLOCKS * 128, W_ELEMS);
        return;
    }
    const int t = blockIdx.x, tid = threadIdx.x;
    float acc[8];
#pragma unroll
    for (int e = 0; e < 8; e++) acc[e] = 0.0f;
    const float* xr = x + (size_t)t * DMODEL;
    __half* x16r = g_x16 + (size_t)t * DMODEL;
    for (int d = tid; d < DMODEL; d += 128) {
        float xv = xr[d];
        x16r[d] = __float2half_rn(xv);
        const float4* w4 = reinterpret_cast<const float4*>(Wg + (size_t)d * 8);
        float4 w0 = w4[0], w1 = w4[1];
        acc[0] += xv * w0.x; acc[1] += xv * w0.y; acc[2] += xv * w0.z; acc[3] += xv * w0.w;
        acc[4] += xv * w1.x; acc[5] += xv * w1.y; acc[6] += xv * w1.z; acc[7] += xv * w1.w;
    }
#pragma unroll
    for (int e = 0; e < 8; e++)
#pragma unroll
        for (int o = 16; o > 0; o >>= 1) acc[e] += __shfl_down_sync(0xffffffffu, acc[e], o);
    __shared__ float sred[4][8];
    int wid = tid >> 5, lane = tid & 31;
    if (lane == 0)
#pragma unroll
        for (int e = 0; e < 8; e++) sred[wid][e] = acc[e];
    __syncthreads();
    if (tid == 0) {
        float l[8];
#pragma unroll
        for (int e = 0; e < 8; e++) l[e] = sred[0][e] + sred[1][e] + sred[2][e] + sred[3][e];
        int i1 = 0;
#pragma unroll
        for (int e = 1; e < 8; e++) if (l[e] > l[i1]) i1 = e;
        int i2 = (i1 == 0) ? 1 : 0;
#pragma unroll
        for (int e = 0; e < 8; e++) if (e != i1 && l[e] > l[i2]) i2 = e;
        float m = l[i1], p[8], s = 0.0f;
#pragma unroll
        for (int e = 0; e < 8; e++) { p[e] = __expf(l[e] - m); s += p[e]; }
        float inv = 1.0f / s;
        int pos1 = atomicAdd(&g_cnt[i1], 1);
        g_tok[i1][pos1] = t; g_gate[i1][pos1] = p[i1] * inv; g_slot[i1][pos1] = 0;
        int pos2 = atomicAdd(&g_cnt[i2], 1);
        g_tok[i2][pos2] = t; g_gate[i2][pos2] = p[i2] * inv; g_slot[i2][pos2] = 1;
    }
}

__global__ void scan_kernel() {
    if (threadIdx.x == 0) {
        int o = 0;
#pragma unroll
        for (int e = 0; e < N_EXP; e++) { g_off[e] = o; o += (g_cnt[e] + 127) & ~127; }
        g_off[N_EXP] = o;
    }
}

__global__ void combine_kernel(float* __restrict__ out) {
    size_t i = ((size_t)blockIdx.x * 256 + threadIdx.x) * 4;
    float4 a = *reinterpret_cast<const float4*>(&g_y[0][i]);
    float4 b = *reinterpret_cast<const float4*>(&g_y[1][i]);
    *reinterpret_cast<float4*>(out + i) =
        make_float4(a.x + b.x, a.y + b.y, a.z + b.z, a.w + b.w);
}

// ---------------- fp16 grouped GEMM: 128(M) x 128(N) x 32(K), 4-stage, 2 CTA/SM ------
// A: K-major fp16 rows, ldmatrix normal. B: native [k][n] fp16, ldmatrix.trans.
// FIRST: blockIdx.z == N_EXP is a fused convert slice for W2 (DRAM-bound filler).
template <bool FIRST>
__global__ void __launch_bounds__(256, 2)
moe_gemm_fp16(const float* __restrict__ bias, const float* __restrict__ W2raw) {
    constexpr int KTOT = FIRST ? DMODEL : DFF;
    constexpr int NDIM = FIRST ? DFF : DMODEL;
    constexpr int KT   = KTOT / 32;

    const int e = blockIdx.z;
    if (FIRST && e == N_EXP) {
        size_t b = (size_t)blockIdx.y * 32 + blockIdx.x;   // 0..1023
        convert_span(W2raw, g_w2h, b * 256 + threadIdx.x,
                     (size_t)CW2_BLOCKS * 256, W_ELEMS);
        return;
    }
    const int cnt = g_cnt[e];
    const int mtile = blockIdx.y;
    if (mtile * 128 >= cnt) return;
    const int ntile = blockIdx.x;
    const int roff = g_off[e];

    extern __shared__ __align__(1024) char smraw[];
    const uint32_t smem_u = smem_u32(smraw);

    const int tid = threadIdx.x;
    const int lane = tid & 31, wid = tid >> 5;
    const int warp_m = (wid & 1) * 64;       // {0,64}
    const int warp_n = (wid >> 1) * 32;      // {0,32,64,96}

    // ---- cp.async staging ----
    const int arow = tid >> 1;
    const int ac0 = (tid & 1) * 2;
    const __half* aptr;
    if (FIRST) {
        int li = mtile * 128 + arow;
        int tok = (li < cnt) ? g_tok[e][li] : g_tok[e][0];
        aptr = g_x16 + (size_t)tok * DMODEL + ac0 * 8;
    } else {
        aptr = g_h16 + (size_t)(roff + mtile * 128 + arow) * DFF + ac0 * 8;
    }
    uint32_t adst[2];
#pragma unroll
    for (int j = 0; j < 2; j++) {
        int c = ac0 + j;
        adst[j] = (uint32_t)(arow * 64 + ((c ^ ((arow >> 1) & 3)) << 4));
    }
    const int brow = tid >> 3;
    const int bc0 = (tid & 7) * 2;
    const __half* bptr = (FIRST ? g_w1h : g_w2h)
        + (size_t)e * KTOT * NDIM + (size_t)brow * NDIM + ntile * 128 + bc0 * 8;
    uint32_t bdst[2];
#pragma unroll
    for (int j = 0; j < 2; j++) {
        int c = bc0 + j;
        bdst[j] = (uint32_t)(A_STAGE + brow * 256 + ((c ^ (brow & 7)) << 4));
    }

    auto issue = [&](int kt) {
        uint32_t base = smem_u + (kt & 3) * STAGE_BYTES;
        const __half* as = aptr + kt * 32;
        const __half* bs = bptr + (size_t)kt * 32 * NDIM;
        cpa16(base + adst[0], as);
        cpa16(base + adst[1], as + 8);
        cpa16(base + bdst[0], bs);
        cpa16(base + bdst[1], bs + 8);
        asm volatile("cp.async.commit_group;\n");
    };

    // ---- ldmatrix address precompute ----
    const int ahi = lane >> 4;
    uint32_t aoff[4], aswz[4];
#pragma unroll
    for (int mf = 0; mf < 4; mf++) {
        int row = warp_m + mf * 16 + (lane & 15);
        aoff[mf] = (uint32_t)(row * 64);
        aswz[mf] = (uint32_t)((row >> 1) & 3);
    }
    const uint32_t brow_l = (uint32_t)((lane & 15) * 256);
    uint32_t bcol[2];
#pragma unroll
    for (int nb = 0; nb < 2; nb++) {
        int chunk = (warp_n >> 3) + nb * 2 + (lane >> 4);
        bcol[nb] = (uint32_t)(A_STAGE + ((chunk ^ (lane & 7)) << 4));
    }

    float acc[4][4][4];
#pragma unroll
    for (int a = 0; a < 4; a++)
#pragma unroll
        for (int b = 0; b < 4; b++)
#pragma unroll
            for (int c = 0; c < 4; c++) acc[a][b][c] = 0.0f;

    issue(0); issue(1); issue(2);

    for (int kt = 0; kt < KT; kt++) {
        if (kt < KT - 2)       asm volatile("cp.async.wait_group 2;\n");
        else if (kt == KT - 2) asm volatile("cp.async.wait_group 1;\n");
        else                   asm volatile("cp.async.wait_group 0;\n");
        __syncthreads();
        if (kt + 3 < KT) issue(kt + 3);
        const uint32_t base = smem_u + (kt & 3) * STAGE_BYTES;

#pragma unroll
        for (int ks = 0; ks < 2; ks++) {
            uint32_t a[4][4];
#pragma unroll
            for (int mf = 0; mf < 4; mf++)
                ldmx4(a[mf], base + aoff[mf] + ((uint32_t)((2 * ks + ahi) ^ aswz[mf]) << 4));
            uint32_t b[2][4];
#pragma unroll
            for (int nb = 0; nb < 2; nb++)
                ldmx4t(b[nb], base + brow_l + ks * 4096 + bcol[nb]);
#pragma unroll
            for (int mf = 0; mf < 4; mf++)
#pragma unroll
                for (int nb = 0; nb < 2; nb++) {
                    mma_f16(acc[mf][2 * nb + 0], a[mf], b[nb][0], b[nb][1]);
                    mma_f16(acc[mf][2 * nb + 1], a[mf], b[nb][2], b[nb][3]);
                }
        }
    }

    // ---- epilogue ----
    const float* bp = bias + (size_t)e * NDIM + (size_t)ntile * 128;
    const int mlo = lane >> 2;
    const int ncol = (lane & 3) * 2;

    if (FIRST) {
#pragma unroll
        for (int mf = 0; mf < 4; mf++) {
#pragma unroll
            for (int half = 0; half < 2; half++) {
                int row = roff + mtile * 128 + warp_m + mf * 16 + mlo + half * 8;
                __half* hr = g_h16 + (size_t)row * DFF + (size_t)ntile * 128;
#pragma unroll
                for (int nf = 0; nf < 4; nf++) {
                    int c = warp_n + nf * 8 + ncol;
                    *reinterpret_cast<half2*>(hr + c) =
                        gelu_h2(acc[mf][nf][half * 2 + 0] + bp[c],
                                acc[mf][nf][half * 2 + 1] + bp[c + 1]);
                }
            }
        }
    } else {
#pragma unroll
        for (int mf = 0; mf < 4; mf++) {
#pragma unroll
            for (int half = 0; half < 2; half++) {
                int li = mtile * 128 + warp_m + mf * 16 + mlo + half * 8;
                if (li < cnt) {
                    int   t  = g_tok[e][li];
                    float w  = g_gate[e][li];
                    int   sl = g_slot[e][li];
                    float* orow = &g_y[sl][(size_t)t * DMODEL + (size_t)ntile * 128];
#pragma unroll
                    for (int nf = 0; nf < 4; nf++) {
                        int c = warp_n + nf * 8 + ncol;
                        float2 v;
                        v.x = (acc[mf][nf][half * 2 + 0] + bp[c])     * w;
                        v.y = (acc[mf][nf][half * 2 + 1] + bp[c + 1]) * w;
                        *reinterpret_cast<float2*>(orow + c) = v;
                    }
                }
            }
        }
    }
}

// ---------------- launch ----------------
extern "C" void kernel_launch(void* const* d_in, const int* in_sizes, int n_in,
                              void* d_out, int out_size) {
    const float* x  = (const float*)d_in[0];
    const float* Wg = (const float*)d_in[1];
    const float* W1 = (const float*)d_in[2];
    const float* b1 = (const float*)d_in[3];
    const float* W2 = (const float*)d_in[4];
    const float* b2 = (const float*)d_in[5];
    float* out = (float*)d_out;

    const int smem_bytes = STAGES * STAGE_BYTES;   // 64 KB
    cudaFuncSetAttribute(moe_gemm_fp16<true>,  cudaFuncAttributeMaxDynamicSharedMemorySize, smem_bytes);
    cudaFuncSetAttribute(moe_gemm_fp16<false>, cudaFuncAttributeMaxDynamicSharedMemorySize, smem_bytes);

    // Launch order keeps moe_gemm_fp16<true> at position 4 (the ncu window).
    reset_kernel<<<1, 32>>>();                                    // 1
    router_kernel<<<T_TOK + CW1_BLOCKS, 128>>>(x, Wg, W1);        // 2 (router || convert W1)
    scan_kernel<<<1, 1>>>();                                      // 3
    moe_gemm_fp16<true ><<<dim3(DFF / 128, 32, N_EXP + 1), 256, smem_bytes>>>(b1, W2);  // 4 (GEMM1 || convert W2)
    moe_gemm_fp16<false><<<dim3(DMODEL / 128, 32, N_EXP), 256, smem_bytes>>>(b2, nullptr);  // 5
    combine_kernel<<<(T_TOK * DMODEL) / 1024, 256>>>(out);        // 6
}

// round 16
// speedup vs baseline: 1.1601x; 1.0068x over previous
#include <cuda_runtime.h>
#include <cuda_fp16.h>
#include <cstdint>

#define T_TOK   4096
#define DMODEL  1024
#define DFF     4096
#define N_EXP   8
#define HCAP    9216
#define STAGES      4
#define A_STAGE     8192                 // 128 rows x 32 k x fp16
#define B_STAGE     8192                 // 32 k-rows x 128 n x fp16
#define STAGE_BYTES (A_STAGE + B_STAGE)  // 16 KB
#define W_ELEMS ((size_t)N_EXP * DMODEL * DFF)   // 32M elements per weight tensor
#define CW1_BLOCKS 2048                  // convert-W1 blocks fused into router launch
#define CW2_BLOCKS 1024                  // convert-W2 blocks fused into GEMM1 launch

// ---------------- device scratch (static) ----------------
__device__ int    g_cnt[N_EXP];
__device__ int    g_off[N_EXP + 1];
__device__ int    g_tok[N_EXP][T_TOK];
__device__ float  g_gate[N_EXP][T_TOK];
__device__ __half g_x16[(size_t)T_TOK * DMODEL];
__device__ __half g_h16[(size_t)HCAP * DFF];
__device__ __half g_w1h[W_ELEMS];   // [e][d][h] native, fp16
__device__ __half g_w2h[W_ELEMS];   // [e][h][d] native, fp16

// ---------------- helpers ----------------
__device__ __forceinline__ uint32_t smem_u32(const void* p) {
    uint32_t a;
    asm("{ .reg .u64 t; cvta.to.shared.u64 t, %1; cvt.u32.u64 %0, t; }" : "=r"(a) : "l"(p));
    return a;
}
// packed-half2 GELU: poly in f32 (FMA pipe), sigmoid in half2 (2 MUFU / 2 outputs)
__device__ __forceinline__ half2 gelu_h2(float x0, float x1) {
    float u0 = 1.5957691216057308f * (x0 + 0.044715f * x0 * x0 * x0);
    float u1 = 1.5957691216057308f * (x1 + 0.044715f * x1 * x1 * x1);
    half2 hx = __floats2half2_rn(x0, x1);
    half2 hu = __floats2half2_rn(u0, u1);
    half2 e  = h2exp(__hneg2(hu));
    half2 s  = h2rcp(__hadd2(__floats2half2_rn(1.0f, 1.0f), e));
    return __hmul2(hx, s);
}
__device__ __forceinline__ void cpa16(uint32_t s, const void* g) {
    asm volatile("cp.async.cg.shared.global [%0], [%1], 16;\n" :: "r"(s), "l"(g));
}
__device__ __forceinline__ void ldmx4(uint32_t r[4], uint32_t addr) {
    asm volatile("ldmatrix.sync.aligned.m8n8.x4.shared.b16 {%0,%1,%2,%3}, [%4];"
                 : "=r"(r[0]), "=r"(r[1]), "=r"(r[2]), "=r"(r[3]) : "r"(addr));
}
__device__ __forceinline__ void ldmx4t(uint32_t r[4], uint32_t addr) {
    asm volatile("ldmatrix.sync.aligned.m8n8.x4.trans.shared.b16 {%0,%1,%2,%3}, [%4];"
                 : "=r"(r[0]), "=r"(r[1]), "=r"(r[2]), "=r"(r[3]) : "r"(addr));
}
__device__ __forceinline__ void mma_f16(float c[4], const uint32_t a[4],
                                        uint32_t b0, uint32_t b1) {
    asm volatile(
        "mma.sync.aligned.m16n8k16.row.col.f32.f16.f16.f32 "
        "{%0,%1,%2,%3}, {%4,%5,%6,%7}, {%8,%9}, {%0,%1,%2,%3};\n"
        : "+f"(c[0]), "+f"(c[1]), "+f"(c[2]), "+f"(c[3])
        : "r"(a[0]), "r"(a[1]), "r"(a[2]), "r"(a[3]), "r"(b0), "r"(b1));
}
// grid-stride fp32 -> fp16 convert, 8 elems per thread per step
__device__ __forceinline__ void convert_span(const float* __restrict__ in, __half* __restrict__ out,
                                             size_t start, size_t stride, size_t total) {
    for (size_t i = start * 8; i < total; i += stride * 8) {
        float4 v0 = *reinterpret_cast<const float4*>(in + i);
        float4 v1 = *reinterpret_cast<const float4*>(in + i + 4);
        half2 h[4];
        h[0] = __floats2half2_rn(v0.x, v0.y); h[1] = __floats2half2_rn(v0.z, v0.w);
        h[2] = __floats2half2_rn(v1.x, v1.y); h[3] = __floats2half2_rn(v1.z, v1.w);
        *reinterpret_cast<uint4*>(out + i) = *reinterpret_cast<uint4*>(h);
    }
}

// ---------------- small kernels ----------------
__global__ void reset_kernel() { if (threadIdx.x < N_EXP) g_cnt[threadIdx.x] = 0; }

// router (+ x->fp16) fused with W1 convert (blocks >= T_TOK)
__global__ void router_kernel(const float* __restrict__ x, const float* __restrict__ Wg,
                              const float* __restrict__ W1) {
    if (blockIdx.x >= T_TOK) {
        size_t b = blockIdx.x - T_TOK;
        convert_span(W1, g_w1h, b * 128 + threadIdx.x,
                     (size_t)CW1_BLOCKS * 128, W_ELEMS);
        return;
    }
    const int t = blockIdx.x, tid = threadIdx.x;
    float acc[8];
#pragma unroll
    for (int e = 0; e < 8; e++) acc[e] = 0.0f;
    const float* xr = x + (size_t)t * DMODEL;
    __half* x16r = g_x16 + (size_t)t * DMODEL;
    for (int d = tid; d < DMODEL; d += 128) {
        float xv = xr[d];
        x16r[d] = __float2half_rn(xv);
        const float4* w4 = reinterpret_cast<const float4*>(Wg + (size_t)d * 8);
        float4 w0 = w4[0], w1 = w4[1];
        acc[0] += xv * w0.x; acc[1] += xv * w0.y; acc[2] += xv * w0.z; acc[3] += xv * w0.w;
        acc[4] += xv * w1.x; acc[5] += xv * w1.y; acc[6] += xv * w1.z; acc[7] += xv * w1.w;
    }
#pragma unroll
    for (int e = 0; e < 8; e++)
#pragma unroll
        for (int o = 16; o > 0; o >>= 1) acc[e] += __shfl_down_sync(0xffffffffu, acc[e], o);
    __shared__ float sred[4][8];
    int wid = tid >> 5, lane = tid & 31;
    if (lane == 0)
#pragma unroll
        for (int e = 0; e < 8; e++) sred[wid][e] = acc[e];
    __syncthreads();
    if (tid == 0) {
        float l[8];
#pragma unroll
        for (int e = 0; e < 8; e++) l[e] = sred[0][e] + sred[1][e] + sred[2][e] + sred[3][e];
        int i1 = 0;
#pragma unroll
        for (int e = 1; e < 8; e++) if (l[e] > l[i1]) i1 = e;
        int i2 = (i1 == 0) ? 1 : 0;
#pragma unroll
        for (int e = 0; e < 8; e++) if (e != i1 && l[e] > l[i2]) i2 = e;
        float m = l[i1], p[8], s = 0.0f;
#pragma unroll
        for (int e = 0; e < 8; e++) { p[e] = __expf(l[e] - m); s += p[e]; }
        float inv = 1.0f / s;
        int pos1 = atomicAdd(&g_cnt[i1], 1);
        g_tok[i1][pos1] = t; g_gate[i1][pos1] = p[i1] * inv;
        int pos2 = atomicAdd(&g_cnt[i2], 1);
        g_tok[i2][pos2] = t; g_gate[i2][pos2] = p[i2] * inv;
    }
}

__global__ void scan_kernel() {
    if (threadIdx.x == 0) {
        int o = 0;
#pragma unroll
        for (int e = 0; e < N_EXP; e++) { g_off[e] = o; o += (g_cnt[e] + 127) & ~127; }
        g_off[N_EXP] = o;
    }
}

// ---------------- fp16 grouped GEMM: 128(M) x 128(N) x 32(K), 4-stage, 2 CTA/SM ------
// A: K-major fp16 rows, ldmatrix normal. B: native [k][n] fp16, ldmatrix.trans.
// FIRST: blockIdx.z == N_EXP is a fused convert slice for W2 (DRAM-bound filler).
// !FIRST: epilogue scatters gate-weighted results into OUT via atomicAdd (2 adds/elem).
template <bool FIRST>
__global__ void __launch_bounds__(256, 2)
moe_gemm_fp16(const float* __restrict__ bias, const float* __restrict__ W2raw,
              float* __restrict__ OUT) {
    constexpr int KTOT = FIRST ? DMODEL : DFF;
    constexpr int NDIM = FIRST ? DFF : DMODEL;
    constexpr int KT   = KTOT / 32;

    const int e = blockIdx.z;
    if (FIRST && e == N_EXP) {
        size_t b = (size_t)blockIdx.y * 32 + blockIdx.x;   // 0..1023
        convert_span(W2raw, g_w2h, b * 256 + threadIdx.x,
                     (size_t)CW2_BLOCKS * 256, W_ELEMS);
        return;
    }
    const int cnt = g_cnt[e];
    const int mtile = blockIdx.y;
    if (mtile * 128 >= cnt) return;
    const int ntile = blockIdx.x;
    const int roff = g_off[e];

    extern __shared__ __align__(1024) char smraw[];
    const uint32_t smem_u = smem_u32(smraw);

    const int tid = threadIdx.x;
    const int lane = tid & 31, wid = tid >> 5;
    const int warp_m = (wid & 1) * 64;       // {0,64}
    const int warp_n = (wid >> 1) * 32;      // {0,32,64,96}

    // ---- cp.async staging ----
    const int arow = tid >> 1;
    const int ac0 = (tid & 1) * 2;
    const __half* aptr;
    if (FIRST) {
        int li = mtile * 128 + arow;
        int tok = (li < cnt) ? g_tok[e][li] : g_tok[e][0];
        aptr = g_x16 + (size_t)tok * DMODEL + ac0 * 8;
    } else {
        aptr = g_h16 + (size_t)(roff + mtile * 128 + arow) * DFF + ac0 * 8;
    }
    uint32_t adst[2];
#pragma unroll
    for (int j = 0; j < 2; j++) {
        int c = ac0 + j;
        adst[j] = (uint32_t)(arow * 64 + ((c ^ ((arow >> 1) & 3)) << 4));
    }
    const int brow = tid >> 3;
    const int bc0 = (tid & 7) * 2;
    const __half* bptr = (FIRST ? g_w1h : g_w2h)
        + (size_t)e * KTOT * NDIM + (size_t)brow * NDIM + ntile * 128 + bc0 * 8;
    uint32_t bdst[2];
#pragma unroll
    for (int j = 0; j < 2; j++) {
        int c = bc0 + j;
        bdst[j] = (uint32_t)(A_STAGE + brow * 256 + ((c ^ (brow & 7)) << 4));
    }

    auto issue = [&](int kt) {
        uint32_t base = smem_u + (kt & 3) * STAGE_BYTES;
        const __half* as = aptr + kt * 32;
        const __half* bs = bptr + (size_t)kt * 32 * NDIM;
        cpa16(base + adst[0], as);
        cpa16(base + adst[1], as + 8);
        cpa16(base + bdst[0], bs);
        cpa16(base + bdst[1], bs + 8);
        asm volatile("cp.async.commit_group;\n");
    };

    // ---- ldmatrix address precompute ----
    const int ahi = lane >> 4;
    uint32_t aoff[4], aswz[4];
#pragma unroll
    for (int mf = 0; mf < 4; mf++) {
        int row = warp_m + mf * 16 + (lane & 15);
        aoff[mf] = (uint32_t)(row * 64);
        aswz[mf] = (uint32_t)((row >> 1) & 3);
    }
    const uint32_t brow_l = (uint32_t)((lane & 15) * 256);
    uint32_t bcol[2];
#pragma unroll
    for (int nb = 0; nb < 2; nb++) {
        int chunk = (warp_n >> 3) + nb * 2 + (lane >> 4);
        bcol[nb] = (uint32_t)(A_STAGE + ((chunk ^ (lane & 7)) << 4));
    }

    float acc[4][4][4];
#pragma unroll
    for (int a = 0; a < 4; a++)
#pragma unroll
        for (int b = 0; b < 4; b++)
#pragma unroll
            for (int c = 0; c < 4; c++) acc[a][b][c] = 0.0f;

    issue(0); issue(1); issue(2);

    for (int kt = 0; kt < KT; kt++) {
        if (kt < KT - 2)       asm volatile("cp.async.wait_group 2;\n");
        else if (kt == KT - 2) asm volatile("cp.async.wait_group 1;\n");
        else                   asm volatile("cp.async.wait_group 0;\n");
        __syncthreads();
        if (kt + 3 < KT) issue(kt + 3);
        const uint32_t base = smem_u + (kt & 3) * STAGE_BYTES;

#pragma unroll
        for (int ks = 0; ks < 2; ks++) {
            uint32_t a[4][4];
#pragma unroll
            for (int mf = 0; mf < 4; mf++)
                ldmx4(a[mf], base + aoff[mf] + ((uint32_t)((2 * ks + ahi) ^ aswz[mf]) << 4));
            uint32_t b[2][4];
#pragma unroll
            for (int nb = 0; nb < 2; nb++)
                ldmx4t(b[nb], base + brow_l + ks * 4096 + bcol[nb]);
#pragma unroll
            for (int mf = 0; mf < 4; mf++)
#pragma unroll
                for (int nb = 0; nb < 2; nb++) {
                    mma_f16(acc[mf][2 * nb + 0], a[mf], b[nb][0], b[nb][1]);
                    mma_f16(acc[mf][2 * nb + 1], a[mf], b[nb][2], b[nb][3]);
                }
        }
    }

    // ---- epilogue ----
    const float* bp = bias + (size_t)e * NDIM + (size_t)ntile * 128;
    const int mlo = lane >> 2;
    const int ncol = (lane & 3) * 2;

    if (FIRST) {
#pragma unroll
        for (int mf = 0; mf < 4; mf++) {
#pragma unroll
            for (int half = 0; half < 2; half++) {
                int row = roff + mtile * 128 + warp_m + mf * 16 + mlo + half * 8;
                __half* hr = g_h16 + (size_t)row * DFF + (size_t)ntile * 128;
#pragma unroll
                for (int nf = 0; nf < 4; nf++) {
                    int c = warp_n + nf * 8 + ncol;
                    *reinterpret_cast<half2*>(hr + c) =
                        gelu_h2(acc[mf][nf][half * 2 + 0] + bp[c],
                                acc[mf][nf][half * 2 + 1] + bp[c + 1]);
                }
            }
        }
    } else {
#pragma unroll
        for (int mf = 0; mf < 4; mf++) {
#pragma unroll
            for (int half = 0; half < 2; half++) {
                int li = mtile * 128 + warp_m + mf * 16 + mlo + half * 8;
                if (li < cnt) {
                    int   t = g_tok[e][li];
                    float w = g_gate[e][li];
                    float* orow = OUT + (size_t)t * DMODEL + (size_t)ntile * 128;
#pragma unroll
                    for (int nf = 0; nf < 4; nf++) {
                        int c = warp_n + nf * 8 + ncol;
                        atomicAdd(orow + c,     (acc[mf][nf][half * 2 + 0] + bp[c])     * w);
                        atomicAdd(orow + c + 1, (acc[mf][nf][half * 2 + 1] + bp[c + 1]) * w);
                    }
                }
            }
        }
    }
}

// ---------------- launch ----------------
extern "C" void kernel_launch(void* const* d_in, const int* in_sizes, int n_in,
                              void* d_out, int out_size) {
    const float* x  = (const float*)d_in[0];
    const float* Wg = (const float*)d_in[1];
    const float* W1 = (const float*)d_in[2];
    const float* b1 = (const float*)d_in[3];
    const float* W2 = (const float*)d_in[4];
    const float* b2 = (const float*)d_in[5];
    float* out = (float*)d_out;

    const int smem_bytes = STAGES * STAGE_BYTES;   // 64 KB
    cudaFuncSetAttribute(moe_gemm_fp16<true>,  cudaFuncAttributeMaxDynamicSharedMemorySize, smem_bytes);
    cudaFuncSetAttribute(moe_gemm_fp16<false>, cudaFuncAttributeMaxDynamicSharedMemorySize, smem_bytes);

    // Launch order keeps moe_gemm_fp16<true> at kernel position 4 (the ncu window).
    cudaMemsetAsync(d_out, 0, (size_t)out_size * sizeof(float));
    reset_kernel<<<1, 32>>>();                                    // 1
    router_kernel<<<T_TOK + CW1_BLOCKS, 128>>>(x, Wg, W1);        // 2 (router || convert W1)
    scan_kernel<<<1, 1>>>();                                      // 3
    moe_gemm_fp16<true ><<<dim3(DFF / 128, 32, N_EXP + 1), 256, smem_bytes>>>(b1, W2, nullptr);  // 4
    moe_gemm_fp16<false><<<dim3(DMODEL / 128, 32, N_EXP), 256, smem_bytes>>>(b2, nullptr, out);  // 5
}